// round 13
// baseline (speedup 1.0000x reference)
#include <cuda_runtime.h>
#include <cuda_bf16.h>
#include <cstdint>

// Problem constants (K=256, N=65536 fixed)
#define KDIM    256
#define NTIME   65536
#define NCHUNK  512
#define CHUNKL  128
#define WARMUP  32

#define NTILES  1024          // 1024 tiles x 64 output columns t = 0..65535
#define TSTEP   148
#define GRID    296           // 2 M-halves x 148; pairs (2t,2t+1) share S tiles

#define CS      36            // u32 (bf16-pair) per k-chunk in permuted smem
#define RS      144           // u32 per row (4 chunks x 36); 576B, 16B-multiple
#define EPI_STRIDE 68         // floats per row of epilogue staging (mult of 4)

// Scratch (device globals; zero-initialized at module load)
__device__ __align__(16) __nv_bfloat16 g_S[(size_t)NTIME * KDIM]; // S[t][k]; row t=0 stays 0
__device__ float g_Mu0[KDIM];
__device__ float g_rowpart[NCHUNK * KDIM];
__device__ float g_partLL[GRID];
__device__ unsigned g_scanCnt;
__device__ unsigned g_gemmCnt;

__device__ __forceinline__ uint32_t pack_bf16(float lo, float hi) {
    __nv_bfloat162 p = __floats2bfloat162_rn(lo, hi);
    return *reinterpret_cast<uint32_t*>(&p);
}

// ---------------------------------------------------------------------------
// Kernel 1: chunked exponential scan (WARMUP makes chunks independent; decay
// <= e^-1 so carry error <= e^-32). Stores bf16 S at t = j+1, coalesced in k.
// Last-arriving block computes Mu0 (deterministic fixed-order sum).
// ---------------------------------------------------------------------------
__global__ __launch_bounds__(256) void scan_kernel(const float* __restrict__ obs,
                                                   const float* __restrict__ Beta) {
    int k = threadIdx.x;
    int c = blockIdx.x;
    float beta  = Beta[k];
    float decay = expf(-beta);

    const float* orow = obs + ((size_t)k << 16);
    int j0 = c << 7;

    float h = 0.f;
    if (c > 0) {
        const float4* wp = (const float4*)(orow + j0 - WARMUP);
        #pragma unroll
        for (int i = 0; i < WARMUP / 4; ++i) {
            float4 v = wp[i];
            h = decay * (h + v.x); h = decay * (h + v.y);
            h = decay * (h + v.z); h = decay * (h + v.w);
        }
    }

    float s = 0.f;
    const float4* mp = (const float4*)(orow + j0);
    __nv_bfloat16* srow = g_S + (((size_t)(j0 + 1)) << 8) + k;
    int nstore = 65535 - j0; if (nstore > CHUNKL) nstore = CHUNKL;

    #pragma unroll 4
    for (int q = 0; q < CHUNKL / 4; ++q) {
        float4 v = mp[q];
        float vv[4] = {v.x, v.y, v.z, v.w};
        #pragma unroll
        for (int e = 0; e < 4; ++e) {
            float o = vv[e];
            s += o;
            h = decay * (h + o);
            int i = (q << 2) + e;
            if (i < nstore) srow[(size_t)i << 8] = __float2bfloat16_rn(beta * h);
        }
    }
    g_rowpart[(c << 8) + k] = s;

    // last-arriving block computes Mu0
    __threadfence();
    __shared__ unsigned lastFlag;
    if (k == 0) lastFlag = atomicAdd(&g_scanCnt, 1);
    __syncthreads();
    if (lastFlag == NCHUNK - 1) {
        float t = 0.f;
        for (int cc = 0; cc < NCHUNK; ++cc) t += g_rowpart[(cc << 8) + k];
        g_Mu0[k] = t * (1.0f / (float)NTIME) / 10.0f + 0.01f;
        if (k == 0) g_scanCnt = 0;
    }
}

// ---------------------------------------------------------------------------
// Kernel 2: fused bf16 MMA GEMM + softplus + lams0/lams1 stores + loglik.
// 2 CTAs per SM, M=128 (half) per CTA, N=64 per tile, K=256. CTA pairs
// (2t, 2t+1) process the same tiles -> shared S reads hit L2.
// Last CTA performs the final deterministic double-precision loglik sum.
// ---------------------------------------------------------------------------
__device__ __forceinline__ void mma_bf16(float* d, uint32_t a0, uint32_t a1,
                                         uint32_t a2, uint32_t a3,
                                         uint32_t b0, uint32_t b1) {
    asm volatile(
        "mma.sync.aligned.m16n8k16.row.col.f32.bf16.bf16.f32 "
        "{%0,%1,%2,%3}, {%4,%5,%6,%7}, {%8,%9}, {%0,%1,%2,%3};"
        : "+f"(d[0]), "+f"(d[1]), "+f"(d[2]), "+f"(d[3])
        : "r"(a0), "r"(a1), "r"(a2), "r"(a3), "r"(b0), "r"(b1));
}

#define SMEM_U32   (128 * RS + 64 * RS)
#define SMEM_BYTES ((SMEM_U32 + 128 + 512) * 4)

__global__ __launch_bounds__(512, 2) void gemm_kernel(const float* __restrict__ obs,
                                                      const float* __restrict__ Alpha,
                                                      float* __restrict__ out) {
    extern __shared__ uint32_t smu[];
    uint32_t* As  = smu;                        // [128][RS] bf16-pairs, permuted
    uint32_t* Ss  = smu + 128 * RS;             // [64][RS]; overlaid as epi[128][EPI_STRIDE]
    float*    epi = (float*)Ss;
    float*   Mu0s = (float*)(smu + SMEM_U32);   // [128] this half
    float*    red = Mu0s + 128;

    int tid   = threadIdx.x;
    int mhalf = blockIdx.x & 1;
    int tile0 = blockIdx.x >> 1;

    // ---- Stage this M-half of Alpha into smem (bf16 pairs, permuted), once.
    {
        int r = tid >> 2, quarter = tid & 3;    // 4 threads/row, 16 float4 each
        const float4* src = (const float4*)(Alpha + (((size_t)((mhalf << 7) + r)) << 8))
                          + quarter * 16;
        uint32_t* dst = As + r * RS;
        #pragma unroll
        for (int i = 0; i < 16; ++i) {
            int f = quarter * 16 + i;           // float4 idx: k = 4f..4f+3, pairs 2f, 2f+1
            float4 v = src[i];
            int j0 = 2 * f, j1 = 2 * f + 1;
            dst[(j0 & 3) * CS + (j0 >> 2)] = pack_bf16(v.x, v.y);
            dst[(j1 & 3) * CS + (j1 >> 2)] = pack_bf16(v.z, v.w);
        }
    }
    if (tid < 128) Mu0s[tid] = g_Mu0[(mhalf << 7) + tid];

    int warp = tid >> 5, lane = tid & 31;
    int wm = warp & 3, wn = warp >> 2;          // 4x4 warp grid: M=32, N=16 per warp
    int g  = lane >> 2, t = lane & 3;
    const uint32_t* aB = As + (wm * 32 + g) * RS + t * CS;
    const uint32_t* bB = Ss + (wn * 16 + g) * RS + t * CS;

    // ---- S tile register prefetch: 64 rows x 128 u32; 8 threads/row, 4 uint4 each.
    int scol = tid >> 3, sq = tid & 7;
    uint4 v[4];
    {
        const uint4* src = (const uint4*)g_S + ((size_t)(tile0 * 64 + scol) * 32) + sq * 4;
        #pragma unroll
        for (int i = 0; i < 4; ++i) v[i] = src[i];
    }

    int erow = tid >> 2;                        // epilogue row 0..127 (local)
    int seg  = (tid & 3) << 4;                  // 16-col contiguous span

    float llacc = 0.f;

    for (int tile = tile0; tile < NTILES; tile += TSTEP) {
        __syncthreads();                        // prev epi reads done; As staged (first iter)
        // STS prefetched S tile (permuted): u32 j -> pos (j&3)*CS + (j>>2)
        {
            uint32_t* dst = Ss + scol * RS;
            #pragma unroll
            for (int i = 0; i < 4; ++i) {
                int u = 4 * sq + i;
                dst[u]          = v[i].x;
                dst[CS + u]     = v[i].y;
                dst[2 * CS + u] = v[i].z;
                dst[3 * CS + u] = v[i].w;
            }
        }
        __syncthreads();
        int ntile = tile + TSTEP;
        if (ntile < NTILES) {                   // overlap next LDG with MMA
            const uint4* src = (const uint4*)g_S + ((size_t)(ntile * 64 + scol) * 32) + sq * 4;
            #pragma unroll
            for (int i = 0; i < 4; ++i) v[i] = src[i];
        }

        float acc[2][2][4];
        #pragma unroll
        for (int mt = 0; mt < 2; ++mt)
            #pragma unroll
            for (int nt = 0; nt < 2; ++nt)
                #pragma unroll
                for (int q = 0; q < 4; ++q) acc[mt][nt][q] = 0.f;

        #pragma unroll
        for (int q = 0; q < 8; ++q) {           // each q = 2 k16 blocks
            uint4 Ag[2], Ah[2], Bn[2];
            #pragma unroll
            for (int mt = 0; mt < 2; ++mt) {
                Ag[mt] = *(const uint4*)(aB + (mt * 16) * RS + 4 * q);
                Ah[mt] = *(const uint4*)(aB + (mt * 16 + 8) * RS + 4 * q);
            }
            #pragma unroll
            for (int nt = 0; nt < 2; ++nt)
                Bn[nt] = *(const uint4*)(bB + (nt * 8) * RS + 4 * q);
            #pragma unroll
            for (int mt = 0; mt < 2; ++mt)
                #pragma unroll
                for (int nt = 0; nt < 2; ++nt) {
                    mma_bf16(acc[mt][nt], Ag[mt].x, Ah[mt].x, Ag[mt].y, Ah[mt].y,
                             Bn[nt].x, Bn[nt].y);
                    mma_bf16(acc[mt][nt], Ag[mt].z, Ah[mt].z, Ag[mt].w, Ah[mt].w,
                             Bn[nt].z, Bn[nt].w);
                }
        }
        __syncthreads();                        // all MMA reads of Ss done

        // ---- Stage all acc rows into epi buffer (single pass, 128 rows).
        #pragma unroll
        for (int mt = 0; mt < 2; ++mt)
            #pragma unroll
            for (int rr = 0; rr < 2; ++rr) {
                int r = wm * 32 + mt * 16 + rr * 8 + g;
                #pragma unroll
                for (int nt = 0; nt < 2; ++nt) {
                    int col = wn * 16 + nt * 8 + 2 * t;
                    *(float2*)(epi + r * EPI_STRIDE + col) =
                        rr == 0 ? make_float2(acc[mt][nt][0], acc[mt][nt][1])
                                : make_float2(acc[mt][nt][2], acc[mt][nt][3]);
                }
            }
        __syncthreads();

        // ---- Coalesced streaming epilogue: 16 contiguous columns per thread.
        {
            float mu = Mu0s[erow];
            size_t grow = ((size_t)((mhalf << 7) + erow)) << 16;
            int t0 = (tile << 6) + seg;
            const float* esrc = epi + erow * EPI_STRIDE + seg;

            float lam[16];
            #pragma unroll
            for (int i = 0; i < 4; ++i) {
                float4 xv = *(const float4*)(esrc + (i << 2));
                float xs[4] = {xv.x, xv.y, xv.z, xv.w};
                #pragma unroll
                for (int e = 0; e < 4; ++e) {
                    float x = xs[e];                      // x >= 0
                    lam[(i << 2) + e] = x + __logf(1.0f + __expf(-x));
                }
            }
            if (tile == 0 && seg == 0) lam[0] = 0.f;      // column t=0: lams1 = 0

            const float4* op = (const float4*)(obs + grow + t0);
            #pragma unroll
            for (int i = 0; i < 4; ++i) {
                float4 ov = op[i];
                llacc += ov.x * __logf(mu + lam[(i << 2) + 0] + 1e-5f) - lam[(i << 2) + 0];
                llacc += ov.y * __logf(mu + lam[(i << 2) + 1] + 1e-5f) - lam[(i << 2) + 1];
                llacc += ov.z * __logf(mu + lam[(i << 2) + 2] + 1e-5f) - lam[(i << 2) + 2];
                llacc += ov.w * __logf(mu + lam[(i << 2) + 3] + 1e-5f) - lam[(i << 2) + 3];
            }
            llacc -= 16.f * mu;

            float* p0 = out + 1 + grow + t0;                           // lams0
            float* p1 = out + 1 + (((size_t)KDIM) << 16) + grow + t0;  // lams1
            // p0/p1 are (16B-4) aligned: 3 scalars, 3x float4, 1 scalar.
            p1[0] = lam[0]; p1[1] = lam[1]; p1[2] = lam[2];
            *(float4*)(p1 + 3)  = make_float4(lam[3],  lam[4],  lam[5],  lam[6]);
            *(float4*)(p1 + 7)  = make_float4(lam[7],  lam[8],  lam[9],  lam[10]);
            *(float4*)(p1 + 11) = make_float4(lam[11], lam[12], lam[13], lam[14]);
            p1[15] = lam[15];
            float4 muv = make_float4(mu, mu, mu, mu);
            p0[0] = mu; p0[1] = mu; p0[2] = mu;
            *(float4*)(p0 + 3) = muv; *(float4*)(p0 + 7) = muv; *(float4*)(p0 + 11) = muv;
            p0[15] = mu;
        }
    }

    // ---- Deterministic CTA reduction of loglik partial.
    __syncthreads();
    red[tid] = llacc;
    __syncthreads();
    for (int off = 256; off > 0; off >>= 1) {
        if (tid < off) red[tid] += red[tid + off];
        __syncthreads();
    }
    if (tid == 0) {
        g_partLL[blockIdx.x] = red[0];
        __threadfence();
    }
    __syncthreads();

    // ---- Last CTA: final deterministic double-precision sum (reuses epi).
    __shared__ unsigned lastFlag;
    if (tid == 0) lastFlag = atomicAdd(&g_gemmCnt, 1);
    __syncthreads();
    if (lastFlag == GRID - 1) {
        double* dred = (double*)epi;
        dred[tid] = (tid < GRID) ? (double)g_partLL[tid] : 0.0;
        __syncthreads();
        for (int off = 256; off > 0; off >>= 1) {
            if (tid < off) dred[tid] += dred[tid + off];
            __syncthreads();
        }
        if (tid == 0) { out[0] = (float)dred[0]; g_gemmCnt = 0; }
    }
}

// ---------------------------------------------------------------------------
extern "C" void kernel_launch(void* const* d_in, const int* in_sizes, int n_in,
                              void* d_out, int out_size) {
    const float* obs   = (const float*)d_in[0];   // [K, N]
    const float* Beta  = (const float*)d_in[1];   // [K]
    const float* Alpha = (const float*)d_in[2];   // [K, K]
    float* out = (float*)d_out;                   // [1 + K*N + K*N]

    scan_kernel<<<NCHUNK, 256>>>(obs, Beta);

    cudaFuncSetAttribute(gemm_kernel, cudaFuncAttributeMaxDynamicSharedMemorySize, SMEM_BYTES);
    gemm_kernel<<<GRID, 512, SMEM_BYTES>>>(obs, Alpha, out);
}

// round 14
// speedup vs baseline: 1.0996x; 1.0996x over previous
#include <cuda_runtime.h>
#include <cuda_bf16.h>
#include <cstdint>

// Problem constants (K=256, N=65536 fixed)
#define KDIM    256
#define NTIME   65536
#define NCHUNK  512
#define CHUNKL  128
#define WARMUP  32

#define NT2     2048          // tiles of 32 output columns
#define TSTEP   148
#define GRID    148           // single wave, persistent tiles

#define CS      36            // u32 (bf16-pair) per k-chunk in permuted smem
#define RS      144           // u32 per row (4 chunks x 36); 576B, 16B-multiple
#define EPIS    36            // floats per row of epilogue staging (mult of 4)

// u32 offsets in dynamic smem
#define OFF_A    0            // [256][RS] u32 = 36864
#define OFF_S    36864        // [32][RS]  u32 = 4608
#define OFF_EPI  41472        // [256][EPIS] floats = 9216
#define OFF_MU   50688        // 256
#define OFF_RED  50944        // 512
#define SMEM_U32 51456
#define SMEM_BYTES (SMEM_U32 * 4)

// Scratch (device globals; zero-initialized at module load)
__device__ __align__(16) __nv_bfloat16 g_S[(size_t)NTIME * KDIM]; // S[t][k]; row t=0 stays 0
__device__ float g_Mu0[KDIM];
__device__ float g_rowpart[NCHUNK * KDIM];
__device__ float g_partLL[GRID];
__device__ unsigned g_scanCnt;
__device__ unsigned g_gemmCnt;

__device__ __forceinline__ uint32_t pack_bf16(float lo, float hi) {
    __nv_bfloat162 p = __floats2bfloat162_rn(lo, hi);
    return *reinterpret_cast<uint32_t*>(&p);
}

// ---------------------------------------------------------------------------
// Kernel 1: chunked exponential scan (WARMUP makes chunks independent; decay
// <= e^-1 so carry error <= e^-32). Stores bf16 S at t = j+1, coalesced in k.
// Last-arriving block computes Mu0 (deterministic fixed-order sum).
// ---------------------------------------------------------------------------
__global__ __launch_bounds__(256) void scan_kernel(const float* __restrict__ obs,
                                                   const float* __restrict__ Beta) {
    int k = threadIdx.x;
    int c = blockIdx.x;
    float beta  = Beta[k];
    float decay = expf(-beta);

    const float* orow = obs + ((size_t)k << 16);
    int j0 = c << 7;

    float h = 0.f;
    if (c > 0) {
        const float4* wp = (const float4*)(orow + j0 - WARMUP);
        #pragma unroll
        for (int i = 0; i < WARMUP / 4; ++i) {
            float4 v = wp[i];
            h = decay * (h + v.x); h = decay * (h + v.y);
            h = decay * (h + v.z); h = decay * (h + v.w);
        }
    }

    float s = 0.f;
    const float4* mp = (const float4*)(orow + j0);
    __nv_bfloat16* srow = g_S + (((size_t)(j0 + 1)) << 8) + k;
    int nstore = 65535 - j0; if (nstore > CHUNKL) nstore = CHUNKL;

    #pragma unroll 4
    for (int q = 0; q < CHUNKL / 4; ++q) {
        float4 v = mp[q];
        float vv[4] = {v.x, v.y, v.z, v.w};
        #pragma unroll
        for (int e = 0; e < 4; ++e) {
            float o = vv[e];
            s += o;
            h = decay * (h + o);
            int i = (q << 2) + e;
            if (i < nstore) srow[(size_t)i << 8] = __float2bfloat16_rn(beta * h);
        }
    }
    g_rowpart[(c << 8) + k] = s;

    // last-arriving block computes Mu0
    __threadfence();
    __shared__ unsigned lastFlag;
    if (k == 0) lastFlag = atomicAdd(&g_scanCnt, 1);
    __syncthreads();
    if (lastFlag == NCHUNK - 1) {
        float t = 0.f;
        for (int cc = 0; cc < NCHUNK; ++cc) t += g_rowpart[(cc << 8) + k];
        g_Mu0[k] = t * (1.0f / (float)NTIME) / 10.0f + 0.01f;
        if (k == 0) g_scanCnt = 0;
    }
}

// ---------------------------------------------------------------------------
// Kernel 2: fused bf16 MMA GEMM + softplus + lams0/lams1 stores + loglik.
// One CTA/SM, M=256, N=32 per tile, K=256. Software-pipelined: MMA of the
// NEXT tile is interleaved with the softplus/streaming epilogue of the
// CURRENT tile (disjoint smem regions -> no barrier between them).
// Last CTA performs the final deterministic double-precision loglik sum.
// ---------------------------------------------------------------------------
__device__ __forceinline__ void mma_bf16(float* d, uint32_t a0, uint32_t a1,
                                         uint32_t a2, uint32_t a3,
                                         uint32_t b0, uint32_t b1) {
    asm volatile(
        "mma.sync.aligned.m16n8k16.row.col.f32.bf16.bf16.f32 "
        "{%0,%1,%2,%3}, {%4,%5,%6,%7}, {%8,%9}, {%0,%1,%2,%3};"
        : "+f"(d[0]), "+f"(d[1]), "+f"(d[2]), "+f"(d[3])
        : "r"(a0), "r"(a1), "r"(a2), "r"(a3), "r"(b0), "r"(b1));
}

__global__ __launch_bounds__(512, 1) void gemm_kernel(const float* __restrict__ obs,
                                                      const float* __restrict__ Alpha,
                                                      float* __restrict__ out) {
    extern __shared__ uint32_t smu[];
    uint32_t* As  = smu + OFF_A;                // [256][RS] bf16-pairs, permuted
    uint32_t* Ss  = smu + OFF_S;                // [32][RS]
    float*    epi = (float*)(smu + OFF_EPI);    // [256][EPIS]
    float*   Mu0s = (float*)(smu + OFF_MU);
    float*    red = (float*)(smu + OFF_RED);

    int tid   = threadIdx.x;
    int tile0 = blockIdx.x;

    // ---- Stage full Alpha into smem (bf16 pairs, permuted), once.
    {
        int r = tid >> 1, half = tid & 1;
        const float4* src = (const float4*)(Alpha + ((size_t)r << 8)) + half * 32;
        uint32_t* dst = As + r * RS;
        #pragma unroll
        for (int i = 0; i < 32; ++i) {
            int f = half * 32 + i;              // float4 idx: k = 4f..4f+3, pairs 2f, 2f+1
            float4 v = src[i];
            int j0 = 2 * f, j1 = 2 * f + 1;
            dst[(j0 & 3) * CS + (j0 >> 2)] = pack_bf16(v.x, v.y);
            dst[(j1 & 3) * CS + (j1 >> 2)] = pack_bf16(v.z, v.w);
        }
    }
    if (tid < 256) Mu0s[tid] = g_Mu0[tid];

    int warp = tid >> 5, lane = tid & 31;
    int wm = warp & 7, wn = warp >> 3;          // 8x2 warp grid: M=32, N=16 per warp
    int g  = lane >> 2, t = lane & 3;
    const uint32_t* aB = As + (wm * 32 + g) * RS + t * CS;
    const uint32_t* bB = Ss + (wn * 16 + g) * RS + t * CS;

    // ---- S tile prefetch: 32 rows x 128 u32; 16 threads/row, 2 uint4 each.
    int scol = tid >> 4, sq = tid & 15;
    uint4 v[2];
    {
        const uint4* src = (const uint4*)g_S + ((size_t)(tile0 * 32 + scol) * 32) + sq * 2;
        v[0] = src[0]; v[1] = src[1];
    }

    int erow = tid >> 1;                        // epilogue row 0..255
    int seg  = (tid & 1) << 4;                  // 16-col contiguous span

    float llacc = 0.f;
    float acc[2][2][4];

    // ---- Prologue: stage S(tile0), MMA(tile0) -> acc.
    __syncthreads();                            // A, Mu0s staged
    {
        uint32_t* dst = Ss + scol * RS;
        #pragma unroll
        for (int i = 0; i < 2; ++i) {
            int u = 2 * sq + i;
            dst[u]          = v[i].x;
            dst[CS + u]     = v[i].y;
            dst[2 * CS + u] = v[i].z;
            dst[3 * CS + u] = v[i].w;
        }
    }
    __syncthreads();
    if (tile0 + TSTEP < NT2) {
        const uint4* src = (const uint4*)g_S +
            ((size_t)((tile0 + TSTEP) * 32 + scol) * 32) + sq * 2;
        v[0] = src[0]; v[1] = src[1];
    }
    #pragma unroll
    for (int mt = 0; mt < 2; ++mt)
        #pragma unroll
        for (int nt = 0; nt < 2; ++nt)
            #pragma unroll
            for (int q = 0; q < 4; ++q) acc[mt][nt][q] = 0.f;
    #pragma unroll
    for (int q = 0; q < 8; ++q) {
        uint4 Ag[2], Ah[2], Bn[2];
        #pragma unroll
        for (int mt = 0; mt < 2; ++mt) {
            Ag[mt] = *(const uint4*)(aB + (mt * 16) * RS + 4 * q);
            Ah[mt] = *(const uint4*)(aB + (mt * 16 + 8) * RS + 4 * q);
        }
        #pragma unroll
        for (int nt = 0; nt < 2; ++nt)
            Bn[nt] = *(const uint4*)(bB + (nt * 8) * RS + 4 * q);
        #pragma unroll
        for (int mt = 0; mt < 2; ++mt)
            #pragma unroll
            for (int nt = 0; nt < 2; ++nt) {
                mma_bf16(acc[mt][nt], Ag[mt].x, Ah[mt].x, Ag[mt].y, Ah[mt].y,
                         Bn[nt].x, Bn[nt].y);
                mma_bf16(acc[mt][nt], Ag[mt].z, Ah[mt].z, Ag[mt].w, Ah[mt].w,
                         Bn[nt].z, Bn[nt].w);
            }
    }

    // ---- Main pipelined loop: epilogue(tile) overlapped with MMA(tile+TSTEP).
    for (int tile = tile0; tile < NT2; tile += TSTEP) {
        int mtile = tile + TSTEP;
        __syncthreads();                        // Ss frag reads done; prev epi reads done

        // Stage acc(tile) -> epi buffer.
        #pragma unroll
        for (int mt = 0; mt < 2; ++mt)
            #pragma unroll
            for (int rr = 0; rr < 2; ++rr) {
                int r = wm * 32 + mt * 16 + rr * 8 + g;
                #pragma unroll
                for (int nt = 0; nt < 2; ++nt) {
                    int col = wn * 16 + nt * 8 + 2 * t;
                    *(float2*)(epi + r * EPIS + col) =
                        rr == 0 ? make_float2(acc[mt][nt][0], acc[mt][nt][1])
                                : make_float2(acc[mt][nt][2], acc[mt][nt][3]);
                }
            }
        // Stage S(mtile) -> Ss.
        if (mtile < NT2) {
            uint32_t* dst = Ss + scol * RS;
            #pragma unroll
            for (int i = 0; i < 2; ++i) {
                int u = 2 * sq + i;
                dst[u]          = v[i].x;
                dst[CS + u]     = v[i].y;
                dst[2 * CS + u] = v[i].z;
                dst[3 * CS + u] = v[i].w;
            }
        }
        __syncthreads();                        // epi + Ss visible

        if (mtile + TSTEP < NT2) {              // prefetch S(mtile+TSTEP)
            const uint4* src = (const uint4*)g_S +
                ((size_t)((mtile + TSTEP) * 32 + scol) * 32) + sq * 2;
            v[0] = src[0]; v[1] = src[1];
        }

        #pragma unroll
        for (int mt = 0; mt < 2; ++mt)
            #pragma unroll
            for (int nt = 0; nt < 2; ++nt)
                #pragma unroll
                for (int q = 0; q < 4; ++q) acc[mt][nt][q] = 0.f;

        const float* esrc = epi + erow * EPIS + seg;
        bool doMMA = mtile < NT2;
        float lam[16];

        // Interleaved: MMA(mtile) q-steps + softplus of 2 cols/q from epi(tile).
        #pragma unroll
        for (int q = 0; q < 8; ++q) {
            if (doMMA) {
                uint4 Ag[2], Ah[2], Bn[2];
                #pragma unroll
                for (int mt = 0; mt < 2; ++mt) {
                    Ag[mt] = *(const uint4*)(aB + (mt * 16) * RS + 4 * q);
                    Ah[mt] = *(const uint4*)(aB + (mt * 16 + 8) * RS + 4 * q);
                }
                #pragma unroll
                for (int nt = 0; nt < 2; ++nt)
                    Bn[nt] = *(const uint4*)(bB + (nt * 8) * RS + 4 * q);
                #pragma unroll
                for (int mt = 0; mt < 2; ++mt)
                    #pragma unroll
                    for (int nt = 0; nt < 2; ++nt) {
                        mma_bf16(acc[mt][nt], Ag[mt].x, Ah[mt].x, Ag[mt].y, Ah[mt].y,
                                 Bn[nt].x, Bn[nt].y);
                        mma_bf16(acc[mt][nt], Ag[mt].z, Ah[mt].z, Ag[mt].w, Ah[mt].w,
                                 Bn[nt].z, Bn[nt].w);
                    }
            }
            {   // softplus for cols 2q, 2q+1 (x >= 0)
                float2 xv = *(const float2*)(esrc + 2 * q);
                lam[2 * q]     = xv.x + __logf(1.0f + __expf(-xv.x));
                lam[2 * q + 1] = xv.y + __logf(1.0f + __expf(-xv.y));
            }
        }
        if (tile == 0 && seg == 0) lam[0] = 0.f;          // column t=0: lams1 = 0

        // Streaming epilogue for (tile): 16 contiguous columns per thread.
        {
            float mu = Mu0s[erow];
            size_t grow = ((size_t)erow) << 16;
            int t0 = (tile << 5) + seg;

            const float4* op = (const float4*)(obs + grow + t0);
            #pragma unroll
            for (int i = 0; i < 4; ++i) {
                float4 ov = op[i];
                llacc += ov.x * __logf(mu + lam[(i << 2) + 0] + 1e-5f) - lam[(i << 2) + 0];
                llacc += ov.y * __logf(mu + lam[(i << 2) + 1] + 1e-5f) - lam[(i << 2) + 1];
                llacc += ov.z * __logf(mu + lam[(i << 2) + 2] + 1e-5f) - lam[(i << 2) + 2];
                llacc += ov.w * __logf(mu + lam[(i << 2) + 3] + 1e-5f) - lam[(i << 2) + 3];
            }
            llacc -= 16.f * mu;

            float* p0 = out + 1 + grow + t0;                           // lams0
            float* p1 = out + 1 + (((size_t)KDIM) << 16) + grow + t0;  // lams1
            // p0/p1 are (16B-4) aligned: 3 scalars, 3x float4, 1 scalar.
            p1[0] = lam[0]; p1[1] = lam[1]; p1[2] = lam[2];
            *(float4*)(p1 + 3)  = make_float4(lam[3],  lam[4],  lam[5],  lam[6]);
            *(float4*)(p1 + 7)  = make_float4(lam[7],  lam[8],  lam[9],  lam[10]);
            *(float4*)(p1 + 11) = make_float4(lam[11], lam[12], lam[13], lam[14]);
            p1[15] = lam[15];
            float4 muv = make_float4(mu, mu, mu, mu);
            p0[0] = mu; p0[1] = mu; p0[2] = mu;
            *(float4*)(p0 + 3) = muv; *(float4*)(p0 + 7) = muv; *(float4*)(p0 + 11) = muv;
            p0[15] = mu;
        }
    }

    // ---- Deterministic CTA reduction of loglik partial.
    __syncthreads();
    red[tid] = llacc;
    __syncthreads();
    for (int off = 256; off > 0; off >>= 1) {
        if (tid < off) red[tid] += red[tid + off];
        __syncthreads();
    }
    if (tid == 0) {
        g_partLL[blockIdx.x] = red[0];
        __threadfence();
    }
    __syncthreads();

    // ---- Last CTA: final deterministic double-precision sum (reuses epi).
    __shared__ unsigned lastFlag;
    if (tid == 0) lastFlag = atomicAdd(&g_gemmCnt, 1);
    __syncthreads();
    if (lastFlag == GRID - 1) {
        double* dred = (double*)epi;
        dred[tid] = (tid < GRID) ? (double)g_partLL[tid] : 0.0;
        __syncthreads();
        for (int off = 256; off > 0; off >>= 1) {
            if (tid < off) dred[tid] += dred[tid + off];
            __syncthreads();
        }
        if (tid == 0) { out[0] = (float)dred[0]; g_gemmCnt = 0; }
    }
}

// ---------------------------------------------------------------------------
extern "C" void kernel_launch(void* const* d_in, const int* in_sizes, int n_in,
                              void* d_out, int out_size) {
    const float* obs   = (const float*)d_in[0];   // [K, N]
    const float* Beta  = (const float*)d_in[1];   // [K]
    const float* Alpha = (const float*)d_in[2];   // [K, K]
    float* out = (float*)d_out;                   // [1 + K*N + K*N]

    scan_kernel<<<NCHUNK, 256>>>(obs, Beta);

    cudaFuncSetAttribute(gemm_kernel, cudaFuncAttributeMaxDynamicSharedMemorySize, SMEM_BYTES);
    gemm_kernel<<<GRID, 512, SMEM_BYTES>>>(obs, Alpha, out);
}